// round 2
// baseline (speedup 1.0000x reference)
#include <cuda_runtime.h>

// MultiBCE collapsed form:
//   total = sum_{b,c} e(b,c) * w(c)
//   e(b,c) = -max(log(arg), -100), arg = y_true ? y_pred : 1 - y_pred
//   w(c)   = (1/C) * sum_h lam[h] * La[h,c]
// Masked (La=0) entries contribute exactly 0 in the reference (log clamp
// makes bce=0 there), so folding the mask into w(c) is exact.

#define BB 512
#define HH 8
#define CC 8192

// N4 float4-groups = 512*8192/4 = 1,048,576 = 1024 blocks * 256 thr * 4 chunks
#define NBLK   1024
#define NTHR   256
#define CHUNKS 4
#define STRIDE (NBLK * NTHR)   // 262144, multiple of 2048 -> w index invariant

__device__ float g_wneg[CC];  // -w(c), so acc = fma(clamped_log, wneg, acc)

__global__ void prep_kernel(const float* __restrict__ La,
                            const float* __restrict__ lam,
                            float* __restrict__ out) {
    int c = blockIdx.x * blockDim.x + threadIdx.x;
    if (c == 0) *out = 0.0f;  // d_out is poisoned; zero before atomics
    if (c < CC) {
        float s = 0.0f;
#pragma unroll
        for (int h = 0; h < HH; ++h)
            s += lam[h] * La[h * CC + c];
        g_wneg[c] = -s * (1.0f / (float)CC);
    }
}

__global__ void __launch_bounds__(NTHR)
bce_reduce_kernel(const float4* __restrict__ yp4,
                  const float4* __restrict__ yt4,
                  float* __restrict__ out) {
    const int tid = blockIdx.x * NTHR + threadIdx.x;   // 0 .. STRIDE-1

    // Column weight: i & 2047 is identical for all 4 chunks (stride is a
    // multiple of 2048), so load the w vector exactly once.
    const float4 w = ((const float4*)g_wneg)[tid & (CC / 4 - 1)];

    // Front-batch all 8 independent 16B streaming loads -> MLP ~ 8/thread.
    float4 p[CHUNKS], t[CHUNKS];
#pragma unroll
    for (int j = 0; j < CHUNKS; ++j) {
        p[j] = __ldcs(yp4 + tid + j * STRIDE);
        t[j] = __ldcs(yt4 + tid + j * STRIDE);
    }

    float acc = 0.0f;
#pragma unroll
    for (int j = 0; j < CHUNKS; ++j) {
        // arg = yt ? yp : 1-yp  (yt is exactly 0.0 or 1.0)
        float a0 = (t[j].x != 0.0f) ? p[j].x : 1.0f - p[j].x;
        float a1 = (t[j].y != 0.0f) ? p[j].y : 1.0f - p[j].y;
        float a2 = (t[j].z != 0.0f) ? p[j].z : 1.0f - p[j].z;
        float a3 = (t[j].w != 0.0f) ? p[j].w : 1.0f - p[j].w;

        // __logf(0) = -inf -> fmaxf gives -100, matching the torch clamp.
        float l0 = fmaxf(__logf(a0), -100.0f);
        float l1 = fmaxf(__logf(a1), -100.0f);
        float l2 = fmaxf(__logf(a2), -100.0f);
        float l3 = fmaxf(__logf(a3), -100.0f);

        acc = fmaf(l0, w.x, acc);
        acc = fmaf(l1, w.y, acc);
        acc = fmaf(l2, w.z, acc);
        acc = fmaf(l3, w.w, acc);
    }

    // warp reduce
#pragma unroll
    for (int o = 16; o > 0; o >>= 1)
        acc += __shfl_down_sync(0xFFFFFFFFu, acc, o);

    __shared__ float smem[NTHR / 32];
    int lane = threadIdx.x & 31;
    int wid  = threadIdx.x >> 5;
    if (lane == 0) smem[wid] = acc;
    __syncthreads();
    if (wid == 0) {
        acc = (lane < NTHR / 32) ? smem[lane] : 0.0f;
#pragma unroll
        for (int o = 4; o > 0; o >>= 1)
            acc += __shfl_down_sync(0xFFFFFFFFu, acc, o);
        if (lane == 0) atomicAdd(out, acc);
    }
}

extern "C" void kernel_launch(void* const* d_in, const int* in_sizes, int n_in,
                              void* d_out, int out_size) {
    const float* y_pred = (const float*)d_in[0];  // [512, 8192] f32
    const float* y_true = (const float*)d_in[1];  // [512, 8192] f32
    const float* La     = (const float*)d_in[2];  // [8, 8192]   f32
    const float* lam    = (const float*)d_in[3];  // [8]         f32
    float* out = (float*)d_out;

    prep_kernel<<<(CC + 255) / 256, 256>>>(La, lam, out);
    bce_reduce_kernel<<<NBLK, NTHR>>>((const float4*)y_pred,
                                      (const float4*)y_true, out);
}

// round 3
// speedup vs baseline: 1.0208x; 1.0208x over previous
#include <cuda_runtime.h>

// MultiBCE collapsed form:
//   total = sum_{b,c} e(b,c) * w(c)
//   e(b,c) = -max(log(arg), -100), arg = y_true ? y_pred : 1-y_pred
//          = -max(log(1 - |y_true - y_pred|), -100)   (y_true in {0,1})
//   w(c)   = (1/C) * sum_h lam[h] * La[h,c]
// Masked (La=0) entries contribute exactly 0 in the reference.

#define BB 512
#define HH 8
#define CC 8192

#define NBLK   1024
#define NTHR   256
#define CHUNKS 4
#define STRIDE (NBLK * NTHR)   // 262144, multiple of 2048 -> w index invariant

__device__ float g_wneg[CC];        // -w(c)
__device__ float g_part[NBLK];      // per-block partial sums
__device__ unsigned int g_ticket;   // completion counter

__global__ void prep_kernel(const float* __restrict__ La,
                            const float* __restrict__ lam) {
    int c = blockIdx.x * blockDim.x + threadIdx.x;
    if (c == 0) g_ticket = 0u;      // reset per launch -> deterministic
    if (c < CC) {
        float s = 0.0f;
#pragma unroll
        for (int h = 0; h < HH; ++h)
            s += lam[h] * La[h * CC + c];
        g_wneg[c] = -s * (1.0f / (float)CC);
    }
}

__global__ void __launch_bounds__(NTHR)
bce_reduce_kernel(const float4* __restrict__ yp4,
                  const float4* __restrict__ yt4,
                  float* __restrict__ out) {
    const int tid = blockIdx.x * NTHR + threadIdx.x;   // 0 .. STRIDE-1

    // One w vector per thread (identical index for all 4 chunks).
    const float4 w = ((const float4*)g_wneg)[tid & (CC / 4 - 1)];

    // Default (.ca) loads: data is L2-resident across graph replays.
    float4 p[CHUNKS], t[CHUNKS];
#pragma unroll
    for (int j = 0; j < CHUNKS; ++j) {
        p[j] = yp4[tid + j * STRIDE];
        t[j] = yt4[tid + j * STRIDE];
    }

    float acc = 0.0f;
#pragma unroll
    for (int j = 0; j < CHUNKS; ++j) {
        // arg = 1 - |t - p|  ==  t ? p : 1-p   (exact for t in {0,1})
        float a0 = 1.0f - fabsf(t[j].x - p[j].x);
        float a1 = 1.0f - fabsf(t[j].y - p[j].y);
        float a2 = 1.0f - fabsf(t[j].z - p[j].z);
        float a3 = 1.0f - fabsf(t[j].w - p[j].w);

        // __logf(0) = -inf -> fmaxf gives -100, matching the torch clamp.
        float l0 = fmaxf(__logf(a0), -100.0f);
        float l1 = fmaxf(__logf(a1), -100.0f);
        float l2 = fmaxf(__logf(a2), -100.0f);
        float l3 = fmaxf(__logf(a3), -100.0f);

        acc = fmaf(l0, w.x, acc);
        acc = fmaf(l1, w.y, acc);
        acc = fmaf(l2, w.z, acc);
        acc = fmaf(l3, w.w, acc);
    }

    // ── block reduce ──
#pragma unroll
    for (int o = 16; o > 0; o >>= 1)
        acc += __shfl_down_sync(0xFFFFFFFFu, acc, o);

    __shared__ float smem[NTHR / 32];
    const int lane = threadIdx.x & 31;
    const int wid  = threadIdx.x >> 5;
    if (lane == 0) smem[wid] = acc;
    __syncthreads();

    __shared__ bool is_last;
    if (wid == 0) {
        acc = (lane < NTHR / 32) ? smem[lane] : 0.0f;
#pragma unroll
        for (int o = 4; o > 0; o >>= 1)
            acc += __shfl_down_sync(0xFFFFFFFFu, acc, o);
        if (lane == 0) {
            g_part[blockIdx.x] = acc;          // spread-address store
            __threadfence();                   // partial visible before ticket
            unsigned int tk = atomicAdd(&g_ticket, 1u);
            is_last = (tk == NBLK - 1);
        }
    }
    __syncthreads();

    // ── last block folds the 1024 partials ──
    if (is_last) {
        float s = 0.0f;
#pragma unroll
        for (int j = 0; j < NBLK / NTHR; ++j)
            s += __ldcg(&g_part[threadIdx.x + j * NTHR]);  // L2, bypass L1
#pragma unroll
        for (int o = 16; o > 0; o >>= 1)
            s += __shfl_down_sync(0xFFFFFFFFu, s, o);
        if (lane == 0) smem[wid] = s;
        __syncthreads();
        if (wid == 0) {
            s = (lane < NTHR / 32) ? smem[lane] : 0.0f;
#pragma unroll
            for (int o = 4; o > 0; o >>= 1)
                s += __shfl_down_sync(0xFFFFFFFFu, s, o);
            if (lane == 0) *out = s;
        }
    }
}

extern "C" void kernel_launch(void* const* d_in, const int* in_sizes, int n_in,
                              void* d_out, int out_size) {
    const float* y_pred = (const float*)d_in[0];  // [512, 8192] f32
    const float* y_true = (const float*)d_in[1];  // [512, 8192] f32
    const float* La     = (const float*)d_in[2];  // [8, 8192]   f32
    const float* lam    = (const float*)d_in[3];  // [8]         f32
    float* out = (float*)d_out;

    prep_kernel<<<(CC + 255) / 256, 256>>>(La, lam);
    bce_reduce_kernel<<<NBLK, NTHR>>>((const float4*)y_pred,
                                      (const float4*)y_true, out);
}